// round 3
// baseline (speedup 1.0000x reference)
#include <cuda_runtime.h>
#include <cuda_fp16.h>
#include <cstdint>

#define OUT_F   4096
#define IN_F    4096
#define M_TOTAL 16384
#define TILE_M  256
#define TILE_N  128
#define TILE_K  32
#define NKTILES (IN_F / TILE_K)          /* 128 */
#define NSTAGE  4
#define NTHREADS 512

/* SMEM rows: 32 halves (64B) padded to 80B */
#define ROW_BYTES   80
#define A_BYTES     (TILE_M * ROW_BYTES)         /* 20480 */
#define B_BYTES     (TILE_N * ROW_BYTES)         /* 10240 */
#define STAGE_BYTES (A_BYTES + B_BYTES)          /* 30720 */
#define SM_TOTAL    (NSTAGE * STAGE_BYTES)       /* 122880 */

/* fp16 operand scratch */
__device__ __half g_Wh[(size_t)OUT_F * IN_F];        /*  32 MB */
__device__ __half g_Xh[(size_t)M_TOTAL * IN_F];      /* 128 MB */

/* ---------------- helpers ---------------- */
__device__ __forceinline__ uint32_t smem_u32(const void* p) {
    uint32_t a;
    asm("{ .reg .u64 t; cvta.to.shared.u64 t, %1; cvt.u32.u64 %0, t; }"
        : "=r"(a) : "l"(p));
    return a;
}
__device__ __forceinline__ void cp16(uint32_t dst, const void* src) {
    asm volatile("cp.async.cg.shared.global [%0], [%1], 16;" :: "r"(dst), "l"(src));
}
__device__ __forceinline__ void ldmatrix_x4(uint32_t* r, uint32_t addr) {
    asm volatile("ldmatrix.sync.aligned.m8n8.x4.shared.b16 {%0,%1,%2,%3}, [%4];"
                 : "=r"(r[0]), "=r"(r[1]), "=r"(r[2]), "=r"(r[3]) : "r"(addr));
}
__device__ __forceinline__ void mma_f16(float* c, const uint32_t* a,
                                        uint32_t b0, uint32_t b1) {
    asm volatile(
        "mma.sync.aligned.m16n8k16.row.col.f32.f16.f16.f32 "
        "{%0,%1,%2,%3}, {%4,%5,%6,%7}, {%8,%9}, {%0,%1,%2,%3};"
        : "+f"(c[0]), "+f"(c[1]), "+f"(c[2]), "+f"(c[3])
        : "r"(a[0]), "r"(a[1]), "r"(a[2]), "r"(a[3]), "r"(b0), "r"(b1));
}

/* -------- pass 1: dequant W -> fp16 -------- */
__global__ void __launch_bounds__(256) dequant_kernel(
    const int* __restrict__ Wq, const float* __restrict__ scale,
    const float* __restrict__ zero)
{
    int t = blockIdx.x * 256 + threadIdx.x;   /* 4 elems per thread */
    int e = t << 2;
    int o = e >> 12;
    int i = e & 4095;
    int g = o >> 6;
    int j = ((o & 63) << 12) + i;
    int4   q = *reinterpret_cast<const int4*>(Wq + (size_t)g * 262144 + j);
    float4 s = *reinterpret_cast<const float4*>(scale + j);
    float4 z = *reinterpret_cast<const float4*>(zero + j);
    __half2 h0 = __floats2half2_rn(((float)q.x - z.x) * s.x,
                                   ((float)q.y - z.y) * s.y);
    __half2 h1 = __floats2half2_rn(((float)q.z - z.z) * s.z,
                                   ((float)q.w - z.w) * s.w);
    uint2 pk;
    pk.x = *reinterpret_cast<uint32_t*>(&h0);
    pk.y = *reinterpret_cast<uint32_t*>(&h1);
    *reinterpret_cast<uint2*>(g_Wh + (size_t)o * IN_F + i) = pk;
}

/* -------- pass 2: x -> fp16 -------- */
__global__ void __launch_bounds__(256) xconv_kernel(const float* __restrict__ x)
{
    size_t t = (size_t)blockIdx.x * 256 + threadIdx.x;
    float4 v = reinterpret_cast<const float4*>(x)[t];
    __half2 h0 = __floats2half2_rn(v.x, v.y);
    __half2 h1 = __floats2half2_rn(v.z, v.w);
    uint2 pk;
    pk.x = *reinterpret_cast<uint32_t*>(&h0);
    pk.y = *reinterpret_cast<uint32_t*>(&h1);
    reinterpret_cast<uint2*>(g_Xh)[t] = pk;
}

/* -------- pass 3: fp16 mma.sync GEMM, 256x128x32, 4-stage cp.async -------- */
__global__ void __launch_bounds__(NTHREADS, 1)
gemm_kernel(const float* __restrict__ bias, float* __restrict__ out)
{
    extern __shared__ char smem[];
    const uint32_t sb = smem_u32(smem);
    const int tid  = threadIdx.x;
    const int wid  = tid >> 5, lane = tid & 31;
    const int m0   = blockIdx.y * TILE_M;
    const int n0   = blockIdx.x * TILE_N;
    const int wm   = wid >> 2;          /* 0..3 : 64 M rows  */
    const int wn   = wid & 3;           /* 0..3 : 32 N cols  */

    /* loader geometry: 1536 16B-chunks per stage (A:1024, B:512), 3/thread */
    uint32_t ld_dst[3];
    const __half* ld_src[3];
    {
        const __half* Xb = g_Xh + (size_t)m0 * IN_F;
        const __half* Wb = g_Wh + (size_t)n0 * IN_F;
#pragma unroll
        for (int j = 0; j < 3; j++) {
            int cid = j * NTHREADS + tid;
            if (cid < 1024) {                       /* A chunk */
                int r = cid >> 2, ch = cid & 3;
                ld_dst[j] = (uint32_t)(r * ROW_BYTES + ch * 16);
                ld_src[j] = Xb + (size_t)r * IN_F + ch * 8;
            } else {                                /* B chunk */
                int bc = cid - 1024;
                int r = bc >> 2, ch = bc & 3;
                ld_dst[j] = (uint32_t)(A_BYTES + r * ROW_BYTES + ch * 16);
                ld_src[j] = Wb + (size_t)r * IN_F + ch * 8;
            }
        }
    }

#define PREFETCH(KT) do {                                                      \
        int _kt = (KT);                                                        \
        uint32_t _st = sb + (uint32_t)((_kt & (NSTAGE - 1)) * STAGE_BYTES);    \
        _Pragma("unroll")                                                      \
        for (int _j = 0; _j < 3; _j++)                                         \
            cp16(_st + ld_dst[_j], ld_src[_j] + _kt * TILE_K);                 \
        asm volatile("cp.async.commit_group;" ::: "memory");                   \
    } while (0)

    PREFETCH(0); PREFETCH(1); PREFETCH(2);

    float acc[4][4][4];                 /* [mt][nt][c] : 64 M x 32 N */
#pragma unroll
    for (int a = 0; a < 4; a++)
#pragma unroll
        for (int b = 0; b < 4; b++)
#pragma unroll
            for (int c = 0; c < 4; c++) acc[a][b][c] = 0.f;

    const uint32_t a_row = (uint32_t)(wm * 64 + (lane & 15));
    const uint32_t b_row = (uint32_t)(wn * 32 + (lane & 15));
    const uint32_t hi    = (uint32_t)(lane >> 4);

    for (int kt = 0; kt < NKTILES; kt++) {
        if (kt < NKTILES - 2)
            asm volatile("cp.async.wait_group 2;" ::: "memory");
        else if (kt == NKTILES - 2)
            asm volatile("cp.async.wait_group 1;" ::: "memory");
        else
            asm volatile("cp.async.wait_group 0;" ::: "memory");
        __syncthreads();

        if (kt + 3 < NKTILES) PREFETCH(kt + 3);

        const uint32_t st = sb + (uint32_t)((kt & (NSTAGE - 1)) * STAGE_BYTES);
#pragma unroll
        for (int ks = 0; ks < 2; ks++) {                 /* two k16 steps */
            const uint32_t ch = (uint32_t)(ks * 2) + hi;
            uint32_t afr[4][4], bfr[2][4];
#pragma unroll
            for (int mt = 0; mt < 4; mt++)
                ldmatrix_x4(afr[mt],
                            st + (a_row + mt * 16) * ROW_BYTES + ch * 16);
#pragma unroll
            for (int nt2 = 0; nt2 < 2; nt2++)
                ldmatrix_x4(bfr[nt2],
                            st + A_BYTES + (b_row + nt2 * 16) * ROW_BYTES + ch * 16);
#pragma unroll
            for (int mt = 0; mt < 4; mt++)
#pragma unroll
                for (int nt = 0; nt < 4; nt++)
                    mma_f16(acc[mt][nt], afr[mt],
                            bfr[nt >> 1][(nt & 1)], bfr[nt >> 1][(nt & 1) + 2]);
        }
    }

    /* epilogue */
    const int rbase = lane >> 2;
    const int cbase = (lane & 3) * 2;
#pragma unroll
    for (int mt = 0; mt < 4; mt++) {
        const int m = m0 + wm * 64 + mt * 16 + rbase;
#pragma unroll
        for (int nt = 0; nt < 4; nt++) {
            const int n = n0 + wn * 32 + nt * 8 + cbase;
            float2 bv = *reinterpret_cast<const float2*>(bias + n);
            float2 v0, v1;
            v0.x = acc[mt][nt][0] + bv.x;
            v0.y = acc[mt][nt][1] + bv.y;
            v1.x = acc[mt][nt][2] + bv.x;
            v1.y = acc[mt][nt][3] + bv.y;
            *reinterpret_cast<float2*>(out + (size_t)m * OUT_F + n)       = v0;
            *reinterpret_cast<float2*>(out + (size_t)(m + 8) * OUT_F + n) = v1;
        }
    }
}

/* ---------------- launch ---------------- */
extern "C" void kernel_launch(void* const* d_in, const int* in_sizes, int n_in,
                              void* d_out, int out_size)
{
    const float* x     = (const float*)d_in[0];
    const int*   Wq    = (const int*)  d_in[1];
    const float* scale = (const float*)d_in[2];
    const float* zero  = (const float*)d_in[3];
    const float* bias  = (const float*)d_in[4];
    float*       out   = (float*)d_out;

    dequant_kernel<<<(OUT_F * IN_F / 4) / 256, 256>>>(Wq, scale, zero);
    xconv_kernel<<<(M_TOTAL * IN_F / 4) / 256, 256>>>(x);

    cudaFuncSetAttribute(gemm_kernel,
                         cudaFuncAttributeMaxDynamicSharedMemorySize, SM_TOTAL);
    dim3 grid(OUT_F / TILE_N, M_TOTAL / TILE_M);     /* (32, 64) x-fastest */
    gemm_kernel<<<grid, NTHREADS, SM_TOTAL>>>(bias, out);
}